// round 16
// baseline (speedup 1.0000x reference)
#include <cuda_runtime.h>
#include <cuda_fp16.h>
#include <math.h>

typedef unsigned long long u64;
typedef unsigned int u32;

#define NEL  16
#define NPV  32
#define PSTR 33
#define BW   2048
#define MR   (BW * NEL)
#define ASTG 40            // stage row stride in fp16 (80B, bank-distinct for ldmatrix)
#define STGA (128 * ASTG)  // elems per stage buffer (10240B)
#define GSM  (8 * STGA * 2)  // 4 A-stages + 4 B-stages = 81920 bytes

__device__ __align__(16) __half g_xc[2][(size_t)MR * 640];   // compact [h|m] x 320
__device__ __align__(16) float  g_s0[(size_t)MR * 256];
__device__ __align__(16) float  g_s1[(size_t)MR * 256];
__device__ __align__(16) float  g_pud[5][(size_t)BW * 1024];
__device__ __align__(16) float  g_base6[6][(size_t)BW * 256];
__device__ __align__(16) float  g_env[MR];
__device__ __align__(16) float  g_sw[(size_t)MR * 128];
__device__ __align__(16) __half g_mcat[(size_t)BW * 1024];   // compact [h|m] x 512
__device__ __align__(16) __half g_wscat[5][256 * 960];       // 3 slots x 320: {wh,wh,wm}
__device__ __align__(16) __half g_wmcat[5][256 * 1536];      // 3 slots x 512
__device__ __align__(16) __half g_worb[256 * 768];           // 3 slots x 256
__device__ __align__(16) float  g_obias[256];
__device__ __align__(16) float  g_sbias[5][256];

__device__ __forceinline__ float fast_tanh(float x) {
    float e, r;
    asm("ex2.approx.f32 %0, %1;" : "=f"(e) : "f"(x * 2.885390082f));
    asm("rcp.approx.f32 %0, %1;" : "=f"(r) : "f"(e + 1.0f));
    return fmaf(-2.0f, r, 1.0f);
}
__device__ __forceinline__ u32 smem_u32(const void* p) {
    u32 a;
    asm("{ .reg .u64 t; cvta.to.shared.u64 t, %1; cvt.u32.u64 %0, t; }" : "=r"(a) : "l"(p));
    return a;
}
__device__ __forceinline__ void split2(float x, __half& h, __half& m) {
    h = __float2half_rn(x);
    m = __float2half_rn(x - __half2float(h));
}
__device__ __forceinline__ u32 pkh(__half a, __half b) {
    return ((u32)__half_as_ushort(b) << 16) | (u32)__half_as_ushort(a);
}
__device__ __forceinline__ void ldmat4(u32* r, u32 addr) {
    asm volatile("ldmatrix.sync.aligned.m8n8.x4.shared.b16 {%0,%1,%2,%3}, [%4];"
                 : "=r"(r[0]), "=r"(r[1]), "=r"(r[2]), "=r"(r[3]) : "r"(addr));
}
__device__ __forceinline__ void mma16816(float* d, const u32* a, const u32* b) {
    asm volatile(
        "mma.sync.aligned.m16n8k16.row.col.f32.f16.f16.f32 "
        "{%0,%1,%2,%3}, {%4,%5,%6,%7}, {%8,%9}, {%0,%1,%2,%3};"
        : "+f"(d[0]), "+f"(d[1]), "+f"(d[2]), "+f"(d[3])
        : "r"(a[0]), "r"(a[1]), "r"(a[2]), "r"(a[3]), "r"(b[0]), "r"(b[1]));
}
__device__ __forceinline__ void cp16(u32 dst, const void* src) {
    asm volatile("cp.async.ca.shared.global [%0], [%1], 16;" :: "r"(dst), "l"(src));
}
#define CP_COMMIT() asm volatile("cp.async.commit_group;" ::: "memory")
#define CP_WAIT2()  asm volatile("cp.async.wait_group 2;" ::: "memory")
__device__ __forceinline__ float* sbuf(int p) { return p ? g_s1 : g_s0; }

// slot j computes A[amap[j]] * W[wver[j]]: h*wh, m*wh, h*wm
__device__ __constant__ int c_amap[3] = {0, 1, 0};

// ---------------- weight prep ----------------
__global__ void prepK(const float* __restrict__ sW, const float* __restrict__ vW,
                      const float* __restrict__ wuW, const float* __restrict__ wdW,
                      const float* __restrict__ sb, const float* __restrict__ vb,
                      const float* __restrict__ wub, const float* __restrict__ wdb) {
    int gt = blockIdx.x * blockDim.x + threadIdx.x, gs = gridDim.x * blockDim.x;
    for (int i = gt; i < 5 * 256 * 960; i += gs) {
        int L = i / (256 * 960), r2 = i % (256 * 960), n = r2 / 960, k = r2 % 960;
        const float* W = (L < 4) ? sW + (size_t)L * 832 * 256 : vW;
        int slot = k / 320, km = k % 320;
        int kr = (km < 256) ? km : 512 + km;
        float v = W[(size_t)kr * 256 + n];
        __half h, m; split2(v, h, m);
        g_wscat[L][n * 960 + k] = (slot < 2) ? h : m;
    }
    for (int i = gt; i < 5 * 256 * 1536; i += gs) {
        int L = i / (256 * 1536), r2 = i % (256 * 1536), n = r2 / 1536, k = r2 % 1536;
        const float* W = (L < 4) ? sW + (size_t)L * 832 * 256 : vW;
        int slot = k / 512;
        int kr = 256 + (k % 512);
        float v = W[(size_t)kr * 256 + n];
        __half h, m; split2(v, h, m);
        g_wmcat[L][n * 1536 + k] = (slot < 2) ? h : m;
    }
    for (int i = gt; i < 256 * 768; i += gs) {
        int n = i / 768, k = i % 768;
        int slot = k / 256, kk = k % 256;
        float v = (n < 128) ? wuW[kk * 128 + n] : wdW[kk * 128 + (n - 128)];
        __half h, m; split2(v, h, m);
        g_worb[n * 768 + k] = (slot < 2) ? h : m;
    }
    for (int i = gt; i < 256; i += gs) g_obias[i] = (i < 128) ? wub[i] : wdb[i - 128];
    for (int i = gt; i < 5 * 256; i += gs) {
        int L = i >> 8, c = i & 255;
        g_sbias[L][c] = (L < 4) ? sb[L * 256 + c] : vb[c];
    }
}

// ---------------- Phase A ----------------
template <int KIN, bool RES>
__device__ void pA_mm(float* p, const float* __restrict__ W, const float* __restrict__ bias,
                      float* pw, float* pbv, int tid) {
    for (int i = tid; i < KIN * NPV; i += 256) pw[i] = __ldg(W + i);
    if (tid < NPV) pbv[tid] = __ldg(bias + tid);
    __syncthreads();
    float* prow = p + tid * PSTR;
    float pin[KIN];
#pragma unroll
    for (int k = 0; k < KIN; ++k) pin[k] = prow[k];
#pragma unroll
    for (int cb = 0; cb < NPV; cb += 4) {
        float4 a = *(const float4*)(pbv + cb);
#pragma unroll
        for (int k = 0; k < KIN; ++k) {
            float4 w = *(const float4*)(pw + k * NPV + cb);
            a.x = fmaf(pin[k], w.x, a.x); a.y = fmaf(pin[k], w.y, a.y);
            a.z = fmaf(pin[k], w.z, a.z); a.w = fmaf(pin[k], w.w, a.w);
        }
        prow[cb + 0] = RES ? fast_tanh(a.x) + pin[cb + 0] : fast_tanh(a.x);
        prow[cb + 1] = RES ? fast_tanh(a.y) + pin[cb + 1] : fast_tanh(a.y);
        prow[cb + 2] = RES ? fast_tanh(a.z) + pin[cb + 2] : fast_tanh(a.z);
        prow[cb + 3] = RES ? fast_tanh(a.w) + pin[cb + 3] : fast_tanh(a.w);
    }
    __syncthreads();
}

__device__ void pA_means(float* dst, const float* p, int tid) {
    for (int idx = tid; idx < 512; idx += 256) {
        int j = idx >> 5, f = idx & 31;
        float a = 0.f, b = 0.f;
#pragma unroll
        for (int i = 0; i < 8; ++i) a += p[(i * NEL + j) * PSTR + f];
#pragma unroll
        for (int i = 8; i < NEL; ++i) b += p[(i * NEL + j) * PSTR + f];
        dst[j * 32 + f] = a * 0.125f;
        dst[512 + j * 32 + f] = b * 0.125f;
    }
    __syncthreads();
}

__global__ void __launch_bounds__(256) phaseAK(
    const float* __restrict__ r, const float* __restrict__ a,
    const float* __restrict__ sW0, const float* __restrict__ sb0,
    const float* __restrict__ pW0, const float* __restrict__ pb0,
    const float* __restrict__ pW, const float* __restrict__ pb) {
    __shared__ float p[256 * PSTR];
    __shared__ float x[256], mu0[16], md0[16], pu0[64], pd0[64];
    __shared__ float pw[1024], pbv[32], r_s[48], a_s[12];
    const int tid = threadIdx.x, b = blockIdx.x;

    if (tid < 48) r_s[tid] = r[b * 48 + tid];
    if (tid >= 64 && tid < 76) a_s[tid - 64] = a[tid - 64];
    __syncthreads();

    if (tid < 16) {
        int e = tid;
        float rx = r_s[e * 3], ry = r_s[e * 3 + 1], rz = r_s[e * 3 + 2];
        float envv = 0.f;
#pragma unroll
        for (int at = 0; at < 4; ++at) {
            float dx = rx - a_s[at * 3], dy = ry - a_s[at * 3 + 1], dz = rz - a_s[at * 3 + 2];
            float l = sqrtf(dx * dx + dy * dy + dz * dz);
            x[e * 16 + at * 4 + 0] = dx; x[e * 16 + at * 4 + 1] = dy;
            x[e * 16 + at * 4 + 2] = dz; x[e * 16 + at * 4 + 3] = l;
            envv += expf(-l);
        }
        g_env[b * 16 + e] = envv;
    }
    {
        int i = tid >> 4, j = tid & 15;
        float dx = r_s[j * 3] - r_s[i * 3];
        float dy = r_s[j * 3 + 1] - r_s[i * 3 + 1];
        float dz = r_s[j * 3 + 2] - r_s[i * 3 + 2];
        float l = (i == j) ? sqrtf(3.0f) : sqrtf(dx * dx + dy * dy + dz * dz);
        float* prow = p + tid * PSTR;
        prow[0] = dx; prow[1] = dy; prow[2] = dz; prow[3] = l;
    }
    __syncthreads();
    if (tid < 16) {
        float mu = 0.f, md = 0.f;
#pragma unroll
        for (int e = 0; e < 8; ++e) mu += x[e * 16 + tid];
#pragma unroll
        for (int e = 8; e < 16; ++e) md += x[e * 16 + tid];
        mu0[tid] = mu * 0.125f; md0[tid] = md * 0.125f;
    }
    if (tid < 128) {
        int half = tid >> 6, t2 = tid & 63, j = t2 >> 2, f = t2 & 3;
        float s = 0.f;
        if (half == 0) {
#pragma unroll
            for (int i = 0; i < 8; ++i) s += p[(i * NEL + j) * PSTR + f];
            pu0[j * 4 + f] = s * 0.125f;
        } else {
#pragma unroll
            for (int i = 8; i < 16; ++i) s += p[(i * NEL + j) * PSTR + f];
            pd0[j * 4 + f] = s * 0.125f;
        }
    }
    __syncthreads();

    {
        int c = tid;
        float acc[16];
#pragma unroll
        for (int e = 0; e < 16; ++e) acc[e] = 0.f;
        float bse = __ldg(sb0 + c);
#pragma unroll
        for (int k = 0; k < 16; ++k) {
            float w = __ldg(sW0 + k * 256 + c);
#pragma unroll
            for (int e = 0; e < 16; ++e) acc[e] = fmaf(x[e * 16 + k], w, acc[e]);
            bse = fmaf(mu0[k], __ldg(sW0 + (16 + k) * 256 + c), bse);
            bse = fmaf(md0[k], __ldg(sW0 + (32 + k) * 256 + c), bse);
        }
#pragma unroll
        for (int f = 0; f < 4; ++f) {
            float wpu = __ldg(sW0 + (48 + f) * 256 + c);
            float wpd = __ldg(sW0 + (52 + f) * 256 + c);
#pragma unroll
            for (int e = 0; e < 16; ++e)
                acc[e] = fmaf(pu0[e * 4 + f], wpu, fmaf(pd0[e * 4 + f], wpd, acc[e]));
        }
        float mu = 0.f, md = 0.f;
        __half h, m;
#pragma unroll
        for (int e = 0; e < 16; ++e) {
            float sv = fast_tanh(acc[e] + bse);
            if (e < 8) mu += sv; else md += sv;
            g_s0[(size_t)(b * 16 + e) * 256 + c] = sv;
            split2(sv, h, m);
            __half* xr = g_xc[0] + (size_t)(b * 16 + e) * 640;
            xr[c] = h; xr[320 + c] = m;
        }
        __half* mr = g_mcat + (size_t)b * 1024;
        split2(mu * 0.125f, h, m); mr[c] = h; mr[512 + c] = m;
        split2(md * 0.125f, h, m); mr[256 + c] = h; mr[768 + c] = m;
    }

    pA_mm<4, false>(p, pW0, pb0, pw, pbv, tid);
    pA_means(&g_pud[0][(size_t)b * 1024], p, tid);
    // fused pudfill(layer 0): write pu/pd fp16 halves into xc[0]
    {
        const float* dsrc = &g_pud[0][(size_t)b * 1024];
        for (int idx = tid; idx < 512; idx += 256) {
            int e = idx >> 5, f = idx & 31;
            float vu = dsrc[e * 32 + f];
            float vd = dsrc[512 + e * 32 + f];
            __half hu, mu_, hd, md_;
            split2(vu, hu, mu_); split2(vd, hd, md_);
            __half* xr = g_xc[0] + (size_t)(b * 16 + e) * 640;
            xr[256 + f] = hu; xr[288 + f] = hd;
            xr[576 + f] = mu_; xr[608 + f] = md_;
        }
    }
#pragma unroll 1
    for (int i = 0; i < 4; ++i) {
        pA_mm<32, true>(p, pW + i * 1024, pb + i * 32, pw, pbv, tid);
        pA_means(&g_pud[i + 1][(size_t)b * 1024], p, tid);
    }
}

// ---------------- cp.async-pipelined mma.sync GEMM (fp16x3) ----------------
// MODE 0: base split-K (z=0..5: slot=z>>1, khalf=z&1) -> g_base6[z]; z==0 adds bias
// MODE 1: s-res layer (+fused means & next-layer pud fill)
// MODE 2: final layer   MODE 3: orbitals
template <int MODE>
__global__ void __launch_bounds__(256, 2) gemmK(int L) {
    extern __shared__ __half smg[];
    const u32 sb_ = smem_u32(smg);
    const int tid = threadIdx.x, lane = tid & 31, warp = tid >> 5;
    const int wm = warp & 3, wn = warp >> 2;
    const int gid = lane >> 2, tig = lane & 3;
    const int z = blockIdx.z;

    const __half *A, *B;
    int lda, ldb, NS;
    if (MODE == 0)      { A = g_mcat;      B = g_wmcat[L]; lda = 1024; ldb = 1536; NS = 8;  }
    else if (MODE == 3) { A = g_xc[1];     B = g_worb;     lda = 640;  ldb = 768;  NS = 24; }
    else                { A = g_xc[L & 1]; B = g_wscat[L]; lda = 640;  ldb = 960;  NS = 30; }
    const int m0 = blockIdx.x * 128, n0 = blockIdx.y * 128;
    const int lrow = tid >> 1, lhalf = tid & 1;

    float acc[2][8][4];
#pragma unroll
    for (int i = 0; i < 2; ++i)
#pragma unroll
        for (int j = 0; j < 8; ++j)
#pragma unroll
            for (int k = 0; k < 4; ++k) acc[i][j][k] = 0.f;

    auto aoff = [&](int t) -> int {
        if (MODE == 0) return c_amap[z >> 1] * 512 + (z & 1) * 256 + t * 32;
        if (MODE == 3) { int sl = t >> 3; return c_amap[sl] * 320 + (t & 7) * 32; }
        int sl = t / 10; return c_amap[sl] * 320 + (t - sl * 10) * 32;
    };
    auto boff = [&](int t) -> int {
        return (MODE == 0) ? ((z >> 1) * 512 + (z & 1) * 256 + t * 32) : t * 32;
    };

    auto load_stage = [&](int t, int bs) {
        const char* as = (const char*)(A + (size_t)(m0 + lrow) * lda + aoff(t)) + lhalf * 32;
        u32 ad = sb_ + (bs * STGA + lrow * ASTG + lhalf * 16) * 2;
        cp16(ad, as); cp16(ad + 16, as + 16);
        const char* bsc = (const char*)(B + (size_t)(n0 + lrow) * ldb + boff(t)) + lhalf * 32;
        u32 bd = sb_ + ((4 + bs) * STGA + lrow * ASTG + lhalf * 16) * 2;
        cp16(bd, bsc); cp16(bd + 16, bsc + 16);
    };

    load_stage(0, 0); CP_COMMIT();
    load_stage(1, 1); CP_COMMIT();
    load_stage(2, 2); CP_COMMIT();

#pragma unroll 1
    for (int s = 0; s < NS; ++s) {
        CP_WAIT2();
        __syncthreads();
        if (s + 3 < NS) load_stage(s + 3, (s + 3) & 3);
        CP_COMMIT();
        const int bs = s & 3;
        const u32 abase = sb_ + (bs * STGA) * 2;
        const u32 bbase = sb_ + ((4 + bs) * STGA) * 2;
#pragma unroll
        for (int j = 0; j < 2; ++j) {
            const int kb = j * 32;
            u32 af[2][4], bq[4][4];
            ldmat4(af[0], abase + (wm * 32 + (lane & 15)) * 80 + kb + (lane >> 4) * 16);
            ldmat4(af[1], abase + (wm * 32 + 16 + (lane & 15)) * 80 + kb + (lane >> 4) * 16);
#pragma unroll
            for (int q = 0; q < 4; ++q)
                ldmat4(bq[q], bbase + (wn * 64 + q * 16 + (lane & 7) + ((lane >> 4) << 3)) * 80
                              + kb + ((lane >> 3) & 1) * 16);
#pragma unroll
            for (int mt = 0; mt < 2; ++mt)
#pragma unroll
                for (int nt = 0; nt < 8; ++nt)
                    mma16816(acc[mt][nt], af[mt], &bq[nt >> 1][(nt & 1) * 2]);
        }
    }

    // epilogue
    const int rb = m0 + wm * 32, cb0 = n0 + wn * 64;
#pragma unroll
    for (int mt = 0; mt < 2; ++mt) {
        const int r0 = rb + mt * 16 + gid, r1 = r0 + 8;
#pragma unroll
        for (int nt = 0; nt < 8; ++nt) {
            const int c = cb0 + nt * 8 + tig * 2;
            float* d = acc[mt][nt];
            if (MODE == 0) {
                float* b6 = g_base6[z];
                float a0 = d[0], a1 = d[1], a2 = d[2], a3 = d[3];
                if (z == 0) {
                    a0 += g_sbias[L][c]; a1 += g_sbias[L][c + 1];
                    a2 += g_sbias[L][c]; a3 += g_sbias[L][c + 1];
                }
                *(float2*)&b6[(size_t)r0 * 256 + c] = make_float2(a0, a1);
                *(float2*)&b6[(size_t)r1 * 256 + c] = make_float2(a2, a3);
            } else if (MODE == 1 || MODE == 2) {
                size_t bi = (size_t)(r0 >> 4) * 256;
                float bc0 = 0.f, bc1 = 0.f;
#pragma unroll
                for (int q = 0; q < 6; ++q) {
                    bc0 += g_base6[q][bi + c];
                    bc1 += g_base6[q][bi + c + 1];
                }
                float v00 = fast_tanh(d[0] + bc0);
                float v01 = fast_tanh(d[1] + bc1);
                float v10 = fast_tanh(d[2] + bc0);
                float v11 = fast_tanh(d[3] + bc1);
                if (MODE == 1) {
                    const float* rs = sbuf(L & 1);
                    float* so = sbuf((L & 1) ^ 1);
                    float2 q0 = *(const float2*)&rs[(size_t)r0 * 256 + c];
                    float2 q1 = *(const float2*)&rs[(size_t)r1 * 256 + c];
                    v00 += q0.x; v01 += q0.y; v10 += q1.x; v11 += q1.y;
                    *(float2*)&so[(size_t)r0 * 256 + c] = make_float2(v00, v01);
                    *(float2*)&so[(size_t)r1 * 256 + c] = make_float2(v10, v11);
                }
                __half h0, m0h, h1, m1h;
                char* x0 = (char*)(g_xc[(L & 1) ^ 1] + (size_t)r0 * 640);
                split2(v00, h0, m0h); split2(v01, h1, m1h);
                *(u32*)(x0 + 2 * c) = pkh(h0, h1);
                *(u32*)(x0 + 2 * (c + 320)) = pkh(m0h, m1h);
                char* x1 = (char*)(g_xc[(L & 1) ^ 1] + (size_t)r1 * 640);
                split2(v10, h0, m0h); split2(v11, h1, m1h);
                *(u32*)(x1 + 2 * c) = pkh(h0, h1);
                *(u32*)(x1 + 2 * (c + 320)) = pkh(m0h, m1h);
                if (MODE == 1) {
                    // fused means: sum over gid (lane = gid*4+tig)
                    float s00 = v00, s01 = v01, s10 = v10, s11 = v11;
#pragma unroll
                    for (int o = 4; o < 32; o <<= 1) {
                        s00 += __shfl_xor_sync(0xffffffffu, s00, o);
                        s01 += __shfl_xor_sync(0xffffffffu, s01, o);
                        s10 += __shfl_xor_sync(0xffffffffu, s10, o);
                        s11 += __shfl_xor_sync(0xffffffffu, s11, o);
                    }
                    if (gid == 0) {
                        int wk = (rb >> 4) + mt;
                        __half hh, mm;
                        __half* mr = g_mcat + (size_t)wk * 1024;
                        split2(s00 * 0.125f, hh, mm); mr[c] = hh;       mr[512 + c] = mm;
                        split2(s01 * 0.125f, hh, mm); mr[c + 1] = hh;   mr[513 + c] = mm;
                        split2(s10 * 0.125f, hh, mm); mr[256 + c] = hh; mr[768 + c] = mm;
                        split2(s11 * 0.125f, hh, mm); mr[257 + c] = hh; mr[769 + c] = mm;
                    }
                }
            } else {
                float b0v = g_obias[c], b1v = g_obias[c + 1];
                if (c < 128) {
                    float ev = g_env[r0];
                    *(float2*)&g_sw[(size_t)r0 * 128 + c] =
                        make_float2((d[0] + b0v) * ev, (d[1] + b1v) * ev);
                } else {
                    float ev = g_env[r1];
                    *(float2*)&g_sw[(size_t)r1 * 128 + (c - 128)] =
                        make_float2((d[2] + b0v) * ev, (d[3] + b1v) * ev);
                }
            }
        }
    }

    // fused pudfill for next layer (MODE 1 only; one n-half does it)
    if (MODE == 1 && blockIdx.y == 0) {
        for (int idx = tid; idx < 128 * 32; idx += 256) {
            int rr = idx >> 5, f = idx & 31;
            int row = m0 + rr;
            int bw = row >> 4, e = row & 15;
            float vu = g_pud[L + 1][(size_t)bw * 1024 + e * 32 + f];
            float vd = g_pud[L + 1][(size_t)bw * 1024 + 512 + e * 32 + f];
            __half hu, mu_, hd, md_;
            split2(vu, hu, mu_); split2(vd, hd, md_);
            __half* xr = g_xc[(L & 1) ^ 1] + (size_t)row * 640;
            xr[256 + f] = hu; xr[288 + f] = hd;
            xr[576 + f] = mu_; xr[608 + f] = md_;
        }
    }
}

// ---------------- slogdet + combine ----------------
__global__ void __launch_bounds__(32) slogdetK(const float* __restrict__ wfW,
                                               float* __restrict__ out) {
    __shared__ float ldv[32], sgv[32];
    const int b = blockIdx.x, t = threadIdx.x;
    const int spin = t >> 4, d = t & 15;
    float M[8][8];
#pragma unroll
    for (int o = 0; o < 8; ++o)
#pragma unroll
        for (int e = 0; e < 8; ++e)
            M[o][e] = g_sw[(size_t)(b * 16 + spin * 8 + e) * 128 + o * 16 + d];
    float ld = 0.f, sg = 1.f;
    for (int k = 0; k < 8; ++k) {
        int piv = k;
        float mx = fabsf(M[k][k]);
        for (int i2 = k + 1; i2 < 8; ++i2) {
            float v = fabsf(M[i2][k]);
            if (v > mx) { mx = v; piv = i2; }
        }
        if (piv != k) {
            for (int j2 = 0; j2 < 8; ++j2) {
                float tt = M[k][j2]; M[k][j2] = M[piv][j2]; M[piv][j2] = tt;
            }
            sg = -sg;
        }
        float pv = M[k][k];
        ld += logf(fabsf(pv));
        if (pv < 0.f) sg = -sg;
        float inv = 1.0f / pv;
        for (int i2 = k + 1; i2 < 8; ++i2) {
            float f = M[i2][k] * inv;
            for (int j2 = k + 1; j2 < 8; ++j2)
                M[i2][j2] = fmaf(-f, M[k][j2], M[i2][j2]);
        }
    }
    ldv[t] = ld; sgv[t] = sg;
    __syncthreads();
    if (t == 0) {
        float m = -3.402823e38f, ldt[16], sgt[16];
#pragma unroll
        for (int dd = 0; dd < 16; ++dd) {
            ldt[dd] = ldv[dd] + ldv[16 + dd];
            sgt[dd] = sgv[dd] * sgv[16 + dd];
            m = fmaxf(m, ldt[dd]);
        }
        float s = 0.f;
#pragma unroll
        for (int dd = 0; dd < 16; ++dd)
            s += sgt[dd] * expf(ldt[dd] - m) * __ldg(wfW + dd);
        out[b] = logf(fabsf(s)) + m;
    }
}

extern "C" void kernel_launch(void* const* d_in, const int* in_sizes, int n_in,
                              void* d_out, int out_size) {
    const float* r   = (const float*)d_in[0];
    const float* a   = (const float*)d_in[1];
    const float* sW0 = (const float*)d_in[2];
    const float* sb0 = (const float*)d_in[3];
    const float* sW  = (const float*)d_in[4];
    const float* sb  = (const float*)d_in[5];
    const float* pW0 = (const float*)d_in[6];
    const float* pb0 = (const float*)d_in[7];
    const float* pW  = (const float*)d_in[8];
    const float* pb  = (const float*)d_in[9];
    const float* vW  = (const float*)d_in[10];
    const float* vb  = (const float*)d_in[11];
    const float* wuW = (const float*)d_in[12];
    const float* wub = (const float*)d_in[13];
    const float* wdW = (const float*)d_in[14];
    const float* wdb = (const float*)d_in[15];
    const float* wfW = (const float*)d_in[16];
    float* out = (float*)d_out;

    cudaFuncSetAttribute(gemmK<0>, cudaFuncAttributeMaxDynamicSharedMemorySize, GSM);
    cudaFuncSetAttribute(gemmK<1>, cudaFuncAttributeMaxDynamicSharedMemorySize, GSM);
    cudaFuncSetAttribute(gemmK<2>, cudaFuncAttributeMaxDynamicSharedMemorySize, GSM);
    cudaFuncSetAttribute(gemmK<3>, cudaFuncAttributeMaxDynamicSharedMemorySize, GSM);

    prepK<<<256, 256>>>(sW, vW, wuW, wdW, sb, vb, wub, wdb);
    phaseAK<<<BW, 256>>>(r, a, sW0, sb0, pW0, pb0, pW, pb);
    for (int l = 0; l < 5; ++l) {
        gemmK<0><<<dim3(16, 2, 6), 256, GSM>>>(l);
        if (l < 4) gemmK<1><<<dim3(256, 2), 256, GSM>>>(l);
        else       gemmK<2><<<dim3(256, 2), 256, GSM>>>(l);
    }
    gemmK<3><<<dim3(256, 2), 256, GSM>>>(0);
    slogdetK<<<BW, 32>>>(wfW, out);
}